// round 3
// baseline (speedup 1.0000x reference)
#include <cuda_runtime.h>
#include <cstdint>

#define CIN   32
#define COUT  64
#define TT    8
#define DDIM  32
#define HDIM  64
#define WDIM  64
#define BDIM  4

// shared memory layout (float offsets)
#define XS_OFF    0
#define XS_SIZE   (CIN * 9 * 68)          // 19584 (reused as reduce buffer in phase B)
#define WS_OFF    (XS_OFF + XS_SIZE)      // 19584
#define WS_SIZE   (256 * 66)              // 16896 (stride 66: <=2-way STS, 8B-aligned rows)
#define TAP_OFF   (WS_OFF + WS_SIZE)      // 36480
#define TAP_SIZE  (256 * 68)              // 17408
#define SD_OFF    (TAP_OFF + TAP_SIZE)    // 53888 (even -> 8B aligned)
#define SD_SIZE   (TT * 27 * 2)           // 432 (stencils pre-duplicated as f32x2)
#define SMEM_FLOATS (SD_OFF + SD_SIZE)    // 54320
#define SMEM_BYTES  (SMEM_FLOATS * 4)     // 217280

// reduce buffer: 3 slices x 64 o x 68 (stride) floats = 13056 <= XS_SIZE, aliases xs
#define RED_STRIDE 68

__device__ __forceinline__ uint64_t dup_f32x2(float v) {
    uint64_t r;
    asm("mov.b64 %0, {%1, %1};" : "=l"(r) : "f"(v));
    return r;
}
__device__ __forceinline__ uint64_t pack_f32x2(float a, float b) {
    uint64_t r;
    asm("mov.b64 %0, {%1, %2};" : "=l"(r) : "f"(a), "f"(b));
    return r;
}
__device__ __forceinline__ void ffma2(uint64_t& d, uint64_t a, uint64_t b) {
    asm("fma.rn.f32x2 %0, %1, %2, %0;" : "+l"(d) : "l"(a), "l"(b));
}
__device__ __forceinline__ void unpack_f32x2(uint64_t v, float& lo, float& hi) {
    asm("mov.b64 {%0, %1}, %2;" : "=f"(lo), "=f"(hi) : "l"(v));
}

__global__ __launch_bounds__(512, 1)
void stencilconv3d_kernel(const float* __restrict__ x,
                          const float* __restrict__ stencils,
                          const float* __restrict__ weight,
                          const float* __restrict__ bias,
                          float* __restrict__ out) {
    extern __shared__ float sm[];
    float* xs  = sm + XS_OFF;
    float* ws  = sm + WS_OFF;
    float* tap = sm + TAP_OFF;
    float* red = sm + XS_OFF;              // aliases xs (dead after phase A)
    uint64_t* sd = (uint64_t*)(sm + SD_OFF);

    const int h0  = blockIdx.x;   // 0..63
    const int d0  = blockIdx.y;   // 0..31
    const int b   = blockIdx.z;   // 0..3
    const int tid = threadIdx.x;

    // ---------- load x tile: 32c x (3d x 3h) x 66w window, zero-padded, stride 68 ----------
    const float* xb = x + (size_t)b * CIN * DDIM * HDIM * WDIM;
    for (int idx = tid; idx < XS_SIZE; idx += 512) {
        int wx  = idx % 68;
        int row = idx / 68;
        int c   = row / 9;
        int rr  = row - c * 9;
        int dz  = rr / 3;
        int hy  = rr - dz * 3;
        int dg  = d0 + dz - 1;
        int hg  = h0 + hy - 1;
        int wg  = wx - 1;
        float v = 0.f;
        if (wx < 66 && (unsigned)dg < DDIM && (unsigned)hg < HDIM && (unsigned)wg < WDIM)
            v = xb[((c * DDIM + dg) * HDIM + hg) * WDIM + wg];
        xs[idx] = v;
    }

    // ---------- load weight transposed: ws[k*66 + o] = weight[o*256 + k] ----------
    for (int idx = tid; idx < COUT * 256; idx += 512) {
        int o = idx >> 8;
        int k = idx & 255;
        ws[k * 66 + o] = weight[idx];
    }

    // ---------- load stencils pre-duplicated: sd[t*27+s] = {v,v} ----------
    if (tid < TT * 27) {
        float v = stencils[(size_t)b * TT * 27 + tid];
        sd[tid] = dup_f32x2(v);
    }

    __syncthreads();

    // ---------- Phase A: thread = (c, 4-point group); all 8 taps per thread ----------
    {
        const int c  = tid >> 4;          // 0..31
        const int pb = (tid & 15) << 2;   // 0..60

        uint64_t acc[TT][2];
        #pragma unroll
        for (int t = 0; t < TT; t++) { acc[t][0] = 0ull; acc[t][1] = 0ull; }

        #pragma unroll 3
        for (int r = 0; r < 9; r++) {
            const float* xr = &xs[(c * 9 + r) * 68 + pb];
            float4 a4 = *(const float4*)xr;           // w0..w3
            float2 b2 = *(const float2*)(xr + 4);     // w4,w5
            uint64_t A0 = pack_f32x2(a4.x, a4.y);     // {w0,w1}
            uint64_t A1 = pack_f32x2(a4.z, a4.w);     // {w2,w3}
            uint64_t B0 = pack_f32x2(a4.y, a4.z);     // {w1,w2}
            uint64_t B1 = pack_f32x2(a4.w, b2.x);     // {w3,w4}
            uint64_t C1 = pack_f32x2(b2.x, b2.y);     // {w4,w5}
            const uint64_t* sr = &sd[r * 3];
            #pragma unroll
            for (int t = 0; t < TT; t++) {
                uint64_t s0 = sr[t * 27 + 0];
                uint64_t s1 = sr[t * 27 + 1];
                uint64_t s2 = sr[t * 27 + 2];
                ffma2(acc[t][0], s0, A0);  ffma2(acc[t][1], s0, A1);
                ffma2(acc[t][0], s1, B0);  ffma2(acc[t][1], s1, B1);
                ffma2(acc[t][0], s2, A1);  ffma2(acc[t][1], s2, C1);
            }
        }

        #pragma unroll
        for (int t = 0; t < TT; t++) {
            float p0, p1, p2, p3;
            unpack_f32x2(acc[t][0], p0, p1);
            unpack_f32x2(acc[t][1], p2, p3);
            *(float4*)&tap[(c * 8 + t) * 68 + pb] = make_float4(p0, p1, p2, p3);
        }
    }

    __syncthreads();

    // ---------- Phase B: y[64o x 64p] = W[64 x 256] * tap[256 x 64] ----------
    // 512 threads = 4 k-slices x (16 o-tiles x 8 p-tiles); thread tile = 4o x 8p
    const int ks = tid >> 7;            // 0..3  k-slice
    const int r_ = tid & 127;
    const int ot = r_ >> 3;             // 0..15
    const int pt = r_ & 7;              // 0..7
    const int o_base = ot << 2;         // 4 outputs
    const int pb     = pt << 3;         // 8 points

    uint64_t acc[4][4];
    #pragma unroll
    for (int i = 0; i < 4; i++)
        #pragma unroll
        for (int j = 0; j < 4; j++) acc[i][j] = 0ull;

    {
        const float* wsp = &ws[(ks * 64) * 66 + o_base];
        const uint64_t* tapp = (const uint64_t*)&tap[(ks * 64) * 68 + pb];

        #pragma unroll 4
        for (int k = 0; k < 64; k++) {
            float2 wa = *(const float2*)(wsp + k * 66);
            float2 wb = *(const float2*)(wsp + k * 66 + 2);
            uint64_t t0 = tapp[k * 34 + 0];
            uint64_t t1 = tapp[k * 34 + 1];
            uint64_t t2 = tapp[k * 34 + 2];
            uint64_t t3 = tapp[k * 34 + 3];
            uint64_t d0_ = dup_f32x2(wa.x);
            uint64_t d1_ = dup_f32x2(wa.y);
            uint64_t d2_ = dup_f32x2(wb.x);
            uint64_t d3_ = dup_f32x2(wb.y);
            ffma2(acc[0][0], d0_, t0); ffma2(acc[0][1], d0_, t1);
            ffma2(acc[0][2], d0_, t2); ffma2(acc[0][3], d0_, t3);
            ffma2(acc[1][0], d1_, t0); ffma2(acc[1][1], d1_, t1);
            ffma2(acc[1][2], d1_, t2); ffma2(acc[1][3], d1_, t3);
            ffma2(acc[2][0], d2_, t0); ffma2(acc[2][1], d2_, t1);
            ffma2(acc[2][2], d2_, t2); ffma2(acc[2][3], d2_, t3);
            ffma2(acc[3][0], d3_, t0); ffma2(acc[3][1], d3_, t1);
            ffma2(acc[3][2], d3_, t2); ffma2(acc[3][3], d3_, t3);
        }
    }

    // slices 1..3 write partials to the reduce buffer (aliases dead xs)
    if (ks > 0) {
        #pragma unroll
        for (int i = 0; i < 4; i++) {
            uint64_t* rp = (uint64_t*)&red[((ks - 1) * 64 + o_base + i) * RED_STRIDE + pb];
            rp[0] = acc[i][0];
            rp[1] = acc[i][1];
            rp[2] = acc[i][2];
            rp[3] = acc[i][3];
        }
    }

    __syncthreads();

    // slice 0 finalizes: add 3 partials + bias, store
    if (ks == 0) {
        #pragma unroll
        for (int i = 0; i < 4; i++) {
            int o = o_base + i;
            float v[8];
            unpack_f32x2(acc[i][0], v[0], v[1]);
            unpack_f32x2(acc[i][1], v[2], v[3]);
            unpack_f32x2(acc[i][2], v[4], v[5]);
            unpack_f32x2(acc[i][3], v[6], v[7]);
            #pragma unroll
            for (int s = 0; s < 3; s++) {
                const float* rp = &red[(s * 64 + o) * RED_STRIDE + pb];
                float4 r0 = *(const float4*)rp;
                float4 r1 = *(const float4*)(rp + 4);
                v[0] += r0.x; v[1] += r0.y; v[2] += r0.z; v[3] += r0.w;
                v[4] += r1.x; v[5] += r1.y; v[6] += r1.z; v[7] += r1.w;
            }
            float bv = __ldg(&bias[o]);
            size_t off = (((size_t)b * COUT + o) * DDIM + d0) * (HDIM * WDIM)
                       + (size_t)h0 * WDIM + pb;
            *(float4*)&out[off]     = make_float4(v[0] + bv, v[1] + bv, v[2] + bv, v[3] + bv);
            *(float4*)&out[off + 4] = make_float4(v[4] + bv, v[5] + bv, v[6] + bv, v[7] + bv);
        }
    }
}

extern "C" void kernel_launch(void* const* d_in, const int* in_sizes, int n_in,
                              void* d_out, int out_size) {
    const float* x        = (const float*)d_in[0];
    const float* stencils = (const float*)d_in[1];
    const float* weight   = (const float*)d_in[2];
    const float* bias     = (const float*)d_in[3];
    float* out = (float*)d_out;

    cudaFuncSetAttribute(stencilconv3d_kernel,
                         cudaFuncAttributeMaxDynamicSharedMemorySize, SMEM_BYTES);
    dim3 grid(HDIM, DDIM, BDIM);   // 64 x 32 x 4 = 8192 blocks
    stencilconv3d_kernel<<<grid, 512, SMEM_BYTES>>>(x, stencils, weight, bias, out);
}

// round 5
// speedup vs baseline: 1.8067x; 1.8067x over previous
#include <cuda_runtime.h>
#include <cstdint>

#define CIN   32
#define COUT  64
#define TT    8
#define DDIM  32
#define HDIM  64
#define WDIM  64

// ---------- smem layout (float word offsets) ----------
#define SP      136                    // A tile row stride (words), 136 % 32 == 8
#define A_OFF   0
#define A_SIZE  (128 * SP)             // 17408 fl : A taps [k_local][p], tf32
#define B_OFF   A_SIZE                 // 17408
#define B_SIZE  16384                  // B weights in mma-fragment layout, tf32
#define XS_OFF  (B_OFF + B_SIZE)       // 33792
#define XS_SIZE (16 * 12 * 68)         // 13056 : x chunk 16c x (3d x 4h) x 68w
#define SD_OFF  (XS_OFF + XS_SIZE)     // 46848 (x4 bytes -> 8B aligned)
#define SD_SIZE (TT * 27 * 2)          // 432   : stencils dup f32x2
#define SMEM_FLOATS (SD_OFF + SD_SIZE) // 47280
#define SMEM_BYTES  (SMEM_FLOATS * 4)  // 189120
#define RED_OFF A_OFF                  // kh reduction buffer aliases dead A tile

// ---------- helpers ----------
__device__ __forceinline__ uint32_t smem_u32(const void* p) {
    uint32_t a;
    asm("{ .reg .u64 t; cvta.to.shared.u64 t, %1; cvt.u32.u64 %0, t; }" : "=r"(a) : "l"(p));
    return a;
}
__device__ __forceinline__ uint64_t pack_f32x2(float a, float b) {
    uint64_t r; asm("mov.b64 %0, {%1, %2};" : "=l"(r) : "f"(a), "f"(b)); return r;
}
__device__ __forceinline__ uint64_t dup_f32x2(float v) {
    uint64_t r; asm("mov.b64 %0, {%1, %1};" : "=l"(r) : "f"(v)); return r;
}
__device__ __forceinline__ void ffma2(uint64_t& d, uint64_t a, uint64_t b) {
    asm("fma.rn.f32x2 %0, %1, %2, %0;" : "+l"(d) : "l"(a), "l"(b));
}
__device__ __forceinline__ void unpack_f32x2(uint64_t v, float& lo, float& hi) {
    asm("mov.b64 {%0, %1}, %2;" : "=f"(lo), "=f"(hi) : "l"(v));
}
__device__ __forceinline__ uint32_t f2tf32(float x) {
    uint32_t r; asm("cvt.rna.tf32.f32 %0, %1;" : "=r"(r) : "f"(x)); return r;
}
__device__ __forceinline__ void sts32(uint32_t a, uint32_t v) {
    asm volatile("st.shared.b32 [%0], %1;" :: "r"(a), "r"(v));
}
__device__ __forceinline__ uint32_t lds32(uint32_t a) {
    uint32_t v; asm volatile("ld.shared.b32 %0, [%1];" : "=r"(v) : "r"(a)); return v;
}
__device__ __forceinline__ void lds64(uint32_t a, uint32_t& x, uint32_t& y) {
    asm volatile("ld.shared.v2.b32 {%0,%1}, [%2];" : "=r"(x), "=r"(y) : "r"(a));
}
__device__ __forceinline__ void mma_tf32(float* c,
                                         uint32_t a0, uint32_t a1, uint32_t a2, uint32_t a3,
                                         uint32_t b0, uint32_t b1) {
    asm volatile("mma.sync.aligned.m16n8k8.row.col.f32.tf32.tf32.f32 "
                 "{%0,%1,%2,%3}, {%4,%5,%6,%7}, {%8,%9}, {%0,%1,%2,%3};"
                 : "+f"(c[0]), "+f"(c[1]), "+f"(c[2]), "+f"(c[3])
                 : "r"(a0), "r"(a1), "r"(a2), "r"(a3), "r"(b0), "r"(b1));
}

__global__ __launch_bounds__(512, 1)
void stencilconv3d_kernel(const float* __restrict__ x,
                          const float* __restrict__ stencils,
                          const float* __restrict__ weight,
                          const float* __restrict__ bias,
                          float* __restrict__ out) {
    extern __shared__ float sm[];
    float* xs  = sm + XS_OFF;
    float* red = sm + RED_OFF;
    uint64_t* sd = (uint64_t*)(sm + SD_OFF);
    const uint32_t smb = smem_u32(sm);

    const int h0  = blockIdx.x;   // 0..31 (pair of h rows)
    const int d0  = blockIdx.y;   // 0..31
    const int b   = blockIdx.z;   // 0..3
    const int tid = threadIdx.x;
    const int wid = tid >> 5;
    const int lane = tid & 31;

    // ---- one-time: weights -> B fragment layout (tf32) ----
    // B_frag[((f*32 + ksg)*32 + l)*2 + r] = tf32(weight[o*256+k]),
    //   o = f*8 + (l>>2), k = ksg*8 + (l&3) + r*4   (m16n8k8 B-fragment mapping)
    for (int idx = tid; idx < COUT * 256; idx += 512) {
        int o = idx >> 8, k = idx & 255;
        int f = o >> 3, ksg = k >> 3;
        int l = ((o & 7) << 2) | (k & 3);
        int r = (k >> 2) & 1;
        int dest = ((f * 32 + ksg) * 32 + l) * 2 + r;
        sts32(smb + (uint32_t)(B_OFF + dest) * 4u, f2tf32(weight[idx]));
    }
    // ---- one-time: stencils (dup f32x2) ----
    if (tid < TT * 27) sd[tid] = dup_f32x2(stencils[(size_t)b * TT * 27 + tid]);

    // phase A thread mapping
    const int c_l  = tid >> 5;            // 0..15 local channel
    const int prow = (lane >> 4) & 1;     // output h sub-row
    const int pb4  = (lane & 15) << 2;    // 4-point w group
    const int jrot = lane >> 3;           // 0..3 store rotation

    // GEMM warp mapping: wid = pt2*4 + ot*2 + kh
    const int pt2 = wid >> 2;             // 0..3 : 32-point tile
    const int ot  = (wid >> 1) & 1;       // 0..1 : 32-cout tile
    const int kh  = wid & 1;              // 0..1 : k-half

    float acc[2][4][4];                   // [m-frag][n-frag][c]
    #pragma unroll
    for (int i = 0; i < 2; i++)
        #pragma unroll
        for (int j = 0; j < 4; j++)
            #pragma unroll
            for (int c = 0; c < 4; c++) acc[i][j][c] = 0.f;

    const size_t x_plane = (size_t)DDIM * HDIM * WDIM;

    for (int chunk = 0; chunk < 2; chunk++) {
        __syncthreads();   // xs + A tile free for reuse

        // ---- load x chunk: 16c x (3d x 4h) x 68w, zero-padded ----
        const float* xb = x + ((size_t)b * CIN + (size_t)chunk * 16) * x_plane;
        for (int idx = tid; idx < XS_SIZE; idx += 512) {
            int wx  = idx % 68;
            int row = idx / 68;
            int cl  = row / 12;
            int rr  = row - cl * 12;
            int dz  = rr >> 2;
            int hq  = rr & 3;
            int dg  = d0 + dz - 1;
            int hg  = h0 * 2 + hq - 1;
            int wg  = wx - 1;
            float v = 0.f;
            if (wx < 66 && (unsigned)dg < DDIM && (unsigned)hg < HDIM && (unsigned)wg < WDIM)
                v = xb[((size_t)cl * DDIM + dg) * HDIM * WDIM + (size_t)hg * WDIM + wg];
            xs[idx] = v;
        }
        __syncthreads();

        // ---- Phase A: 8 taps x 4 points for (c_l, prow, pb4), fp32 FFMA2 ----
        uint64_t pa[TT][2];
        #pragma unroll
        for (int t = 0; t < TT; t++) { pa[t][0] = 0ull; pa[t][1] = 0ull; }

        #pragma unroll 3
        for (int r = 0; r < 9; r++) {
            const int rr = (r / 3) * 4 + (r % 3) + prow;
            const float* xr = &xs[(c_l * 12 + rr) * 68 + pb4];
            float4 a4 = *(const float4*)xr;
            float2 b2 = *(const float2*)(xr + 4);
            uint64_t A0 = pack_f32x2(a4.x, a4.y);
            uint64_t A1 = pack_f32x2(a4.z, a4.w);
            uint64_t B0 = pack_f32x2(a4.y, a4.z);
            uint64_t B1 = pack_f32x2(a4.w, b2.x);
            uint64_t C1 = pack_f32x2(b2.x, b2.y);
            const uint64_t* sr = &sd[r * 3];
            #pragma unroll
            for (int t = 0; t < TT; t++) {
                uint64_t s0 = sr[t * 27 + 0];
                uint64_t s1 = sr[t * 27 + 1];
                uint64_t s2 = sr[t * 27 + 2];
                ffma2(pa[t][0], s0, A0);  ffma2(pa[t][1], s0, A1);
                ffma2(pa[t][0], s1, B0);  ffma2(pa[t][1], s1, B1);
                ffma2(pa[t][0], s2, A1);  ffma2(pa[t][1], s2, C1);
            }
        }

        float v[TT][4];
        #pragma unroll
        for (int t = 0; t < TT; t++) {
            unpack_f32x2(pa[t][0], v[t][0], v[t][1]);
            unpack_f32x2(pa[t][1], v[t][2], v[t][3]);
        }

        // ---- store taps -> A[k_local][p] tf32, lane-rotated conflict-free STS.32 ----
        #pragma unroll
        for (int t = 0; t < TT; t++) {
            uint32_t rowb = smb + (uint32_t)(A_OFF + (c_l * 8 + t) * SP + prow * 64 + pb4) * 4u;
            #pragma unroll
            for (int s = 0; s < 4; s++) {
                int j = (s + jrot) & 3;
                sts32(rowb + (uint32_t)j * 4u, f2tf32(v[t][j]));
            }
        }
        __syncthreads();

        // ---- GEMM: accumulate this chunk's 128 k via m16n8k8 tf32 ----
        #pragma unroll
        for (int ks = 0; ks < 8; ks++) {
            const int ksl = kh * 8 + ks;          // 0..15 local k-step
            const int kb  = ksl * 8;
            uint32_t abase = smb + (uint32_t)(A_OFF + (kb + (lane & 3)) * SP
                                              + pt2 * 32 + (lane >> 2)) * 4u;
            uint32_t a0[2], a1[2], a2[2], a3[2];
            #pragma unroll
            for (int mf = 0; mf < 2; mf++) {
                uint32_t ab = abase + (uint32_t)(mf * 16) * 4u;
                a0[mf] = lds32(ab);
                a1[mf] = lds32(ab + 8u * 4u);
                a2[mf] = lds32(ab + (uint32_t)(4 * SP) * 4u);
                a3[mf] = lds32(ab + (uint32_t)(4 * SP + 8) * 4u);
            }
            const int ksg = chunk * 16 + ksl;
            #pragma unroll
            for (int nf = 0; nf < 4; nf++) {
                int f = ot * 4 + nf;
                uint32_t b0, b1;
                lds64(smb + (uint32_t)(B_OFF + ((f * 32 + ksg) * 32 + lane) * 2) * 4u, b0, b1);
                mma_tf32(acc[0][nf], a0[0], a1[0], a2[0], a3[0], b0, b1);
                mma_tf32(acc[1][nf], a0[1], a1[1], a2[1], a3[1], b0, b1);
            }
        }
    }

    // ---- reduce k-halves through smem (aliases dead A tile) ----
    __syncthreads();
    const int grp = pt2 * 2 + ot;   // 0..7
    if (kh == 1) {
        #pragma unroll
        for (int mf = 0; mf < 2; mf++)
            #pragma unroll
            for (int nf = 0; nf < 4; nf++)
                #pragma unroll
                for (int c = 0; c < 4; c++)
                    red[(grp * 32 + lane) * 33 + (mf * 16 + nf * 4 + c)] = acc[mf][nf][c];
    }
    __syncthreads();

    if (kh == 0) {
        const size_t ostride = (size_t)DDIM * HDIM * WDIM;
        const float* rp = &red[(grp * 32 + lane) * 33];
        #pragma unroll
        for (int nf = 0; nf < 4; nf++) {
            int o0 = ot * 32 + nf * 8 + (lane & 3) * 2;
            float bv0 = __ldg(&bias[o0]);
            float bv1 = __ldg(&bias[o0 + 1]);
            #pragma unroll
            for (int mf = 0; mf < 2; mf++) {
                #pragma unroll
                for (int c = 0; c < 4; c++) {
                    float s = acc[mf][nf][c] + rp[mf * 16 + nf * 4 + c];
                    int o = o0 + (c & 1);
                    int p = pt2 * 32 + mf * 16 + (lane >> 2) + ((c >> 1) & 1) * 8;
                    int h = h0 * 2 + (p >> 6);
                    int w = p & 63;
                    out[((size_t)b * COUT + o) * ostride
                        + (size_t)d0 * HDIM * WDIM + (size_t)h * WDIM + w]
                        = s + ((c & 1) ? bv1 : bv0);
                }
            }
        }
    }
}

extern "C" void kernel_launch(void* const* d_in, const int* in_sizes, int n_in,
                              void* d_out, int out_size) {
    const float* x        = (const float*)d_in[0];
    const float* stencils = (const float*)d_in[1];
    const float* weight   = (const float*)d_in[2];
    const float* bias     = (const float*)d_in[3];
    float* out = (float*)d_out;

    cudaFuncSetAttribute(stencilconv3d_kernel,
                         cudaFuncAttributeMaxDynamicSharedMemorySize, SMEM_BYTES);
    dim3 grid(HDIM / 2, DDIM, 4);   // 32 x 32 x 4 = 4096 blocks
    stencilconv3d_kernel<<<grid, 512, SMEM_BYTES>>>(x, stencils, weight, bias, out);
}

// round 6
// speedup vs baseline: 1.9092x; 1.0567x over previous
#include <cuda_runtime.h>
#include <cstdint>

#define CIN   32
#define COUT  64
#define TT    8
#define DDIM  32
#define HDIM  64
#define WDIM  64

// ---------- smem layout (float word offsets) ----------
#define SP      132                    // A tile row stride (words); (4r+q) mod 32 distinct
#define A_OFF   0
#define A_SIZE  (128 * SP)             // 16896 fl : A taps [k_local][p], tf32
#define XS_OFF  A_SIZE                 // 16896
#define XS_SIZE (16 * 12 * 68)         // 13056 : x chunk 16c x (3d x 4h) x 68w
#define SD_OFF  (XS_OFF + XS_SIZE)     // 29952 (x4 = 119808 B, 16B aligned)
#define SD_SIZE (9 * 8 * 4 * 2)        // 576 fl : stencils [r][t][4 u64 padded], dup f32x2
#define SMEM_FLOATS (SD_OFF + SD_SIZE) // 30528
#define SMEM_BYTES  (SMEM_FLOATS * 4)  // 122112
#define RED_OFF A_OFF                  // kh reduction buffer aliases dead A tile

// weight fragments (tf32, mma B-fragment layout), computed once per launch
__device__ uint32_t g_wfrag[COUT * 256];

// ---------- helpers ----------
__device__ __forceinline__ uint32_t smem_u32(const void* p) {
    uint32_t a;
    asm("{ .reg .u64 t; cvta.to.shared.u64 t, %1; cvt.u32.u64 %0, t; }" : "=r"(a) : "l"(p));
    return a;
}
__device__ __forceinline__ uint64_t pack_f32x2(float a, float b) {
    uint64_t r; asm("mov.b64 %0, {%1, %2};" : "=l"(r) : "f"(a), "f"(b)); return r;
}
__device__ __forceinline__ uint64_t dup_f32x2(float v) {
    uint64_t r; asm("mov.b64 %0, {%1, %1};" : "=l"(r) : "f"(v)); return r;
}
__device__ __forceinline__ void ffma2(uint64_t& d, uint64_t a, uint64_t b) {
    asm("fma.rn.f32x2 %0, %1, %2, %0;" : "+l"(d) : "l"(a), "l"(b));
}
__device__ __forceinline__ void unpack_f32x2(uint64_t v, float& lo, float& hi) {
    asm("mov.b64 {%0, %1}, %2;" : "=f"(lo), "=f"(hi) : "l"(v));
}
__device__ __forceinline__ uint32_t f2tf32(float x) {
    uint32_t r; asm("cvt.rna.tf32.f32 %0, %1;" : "=r"(r) : "f"(x)); return r;
}
__device__ __forceinline__ void sts32(uint32_t a, uint32_t v) {
    asm volatile("st.shared.b32 [%0], %1;" :: "r"(a), "r"(v));
}
__device__ __forceinline__ uint32_t lds32(uint32_t a) {
    uint32_t v; asm volatile("ld.shared.b32 %0, [%1];" : "=r"(v) : "r"(a)); return v;
}
__device__ __forceinline__ void mma_tf32(float* c,
                                         uint32_t a0, uint32_t a1, uint32_t a2, uint32_t a3,
                                         uint32_t b0, uint32_t b1) {
    asm volatile("mma.sync.aligned.m16n8k8.row.col.f32.tf32.tf32.f32 "
                 "{%0,%1,%2,%3}, {%4,%5,%6,%7}, {%8,%9}, {%0,%1,%2,%3};"
                 : "+f"(c[0]), "+f"(c[1]), "+f"(c[2]), "+f"(c[3])
                 : "r"(a0), "r"(a1), "r"(a2), "r"(a3), "r"(b0), "r"(b1));
}

// ---------- init kernel: weight -> mma B-fragment layout (tf32), once ----------
__global__ void init_wfrag_kernel(const float* __restrict__ weight) {
    int idx = blockIdx.x * 512 + threadIdx.x;   // 0 .. 16383
    int o = idx >> 8, k = idx & 255;
    int f = o >> 3, ksg = k >> 3;
    int l = ((o & 7) << 2) | (k & 3);
    int r = (k >> 2) & 1;
    g_wfrag[((f * 32 + ksg) * 32 + l) * 2 + r] = f2tf32(weight[idx]);
}

__global__ __launch_bounds__(512, 1)
void stencilconv3d_kernel(const float* __restrict__ x,
                          const float* __restrict__ stencils,
                          const float* __restrict__ bias,
                          float* __restrict__ out) {
    extern __shared__ float sm[];
    float* xs  = sm + XS_OFF;
    float* red = sm + RED_OFF;
    uint64_t* sd = (uint64_t*)(sm + SD_OFF);
    const uint32_t smb = smem_u32(sm);

    const int h0  = blockIdx.x;   // 0..31 (pair of h rows)
    const int d0  = blockIdx.y;   // 0..31
    const int b   = blockIdx.z;   // 0..3
    const int tid = threadIdx.x;
    const int wid = tid >> 5;
    const int lane = tid & 31;

    // ---- stencils -> sd[r][t][4] (dup f32x2, padded for LDS.128 pairing) ----
    if (tid < TT * 27) {
        int t = tid / 27, s27 = tid - t * 27;
        int r = s27 / 3,  j  = s27 - r * 3;
        sd[r * 32 + t * 4 + j] = dup_f32x2(stencils[(size_t)b * TT * 27 + tid]);
    }

    // phase A thread mapping
    const int c_l  = tid >> 5;            // 0..15 local channel
    const int prow = (lane >> 4) & 1;     // output h sub-row
    const int pb4  = (lane & 15) << 2;    // 4-point w group
    const int jrot = lane >> 3;           // 0..3 store rotation

    // GEMM warp mapping: wid = pt2*4 + ot*2 + kh
    const int pt2 = wid >> 2;             // 0..3 : 32-point tile
    const int ot  = (wid >> 1) & 1;       // 0..1 : 32-cout tile
    const int kh  = wid & 1;              // 0..1 : k-half

    float acc[2][4][4];                   // [m-frag][n-frag][c]
    #pragma unroll
    for (int i = 0; i < 2; i++)
        #pragma unroll
        for (int j = 0; j < 4; j++)
            #pragma unroll
            for (int c = 0; c < 4; c++) acc[i][j][c] = 0.f;

    const size_t x_plane = (size_t)DDIM * HDIM * WDIM;
    const uint2* gw = (const uint2*)g_wfrag;

    for (int chunk = 0; chunk < 2; chunk++) {
        __syncthreads();   // xs + A tile free for reuse

        // ---- load x chunk: 16c x (3d x 4h) x 68w, zero-padded ----
        // incremental index decomposition: idx = ((cl*12 + rr) * 68) + wx
        const float* xb = x + ((size_t)b * CIN + (size_t)chunk * 16) * x_plane;
        {
            int wx  = tid % 68;
            int row = tid / 68;          // 0..7 at start
            int cl  = 0;
            int rr  = row;               // row < 12 initially
            const int hbase = h0 * 2 - 1;
            for (int idx = tid; idx < XS_SIZE; idx += 512) {
                int dg = d0 + (rr >> 2) - 1;
                int hg = hbase + (rr & 3);
                int wg = wx - 1;
                float v = 0.f;
                if (wx < 66 && (unsigned)dg < DDIM && (unsigned)hg < HDIM && (unsigned)wg < WDIM)
                    v = xb[((size_t)cl * DDIM + dg) * HDIM * WDIM + (size_t)hg * WDIM + wg];
                xs[idx] = v;
                // advance by 512 = 7*68 + 36
                wx += 36; rr += 7;
                if (wx >= 68) { wx -= 68; rr++; }
                if (rr >= 12) { rr -= 12; cl++; }
            }
        }
        __syncthreads();

        // ---- Phase A: 8 taps x 4 points for (c_l, prow, pb4), fp32 FFMA2 ----
        uint64_t pa[TT][2];
        #pragma unroll
        for (int t = 0; t < TT; t++) { pa[t][0] = 0ull; pa[t][1] = 0ull; }

        #pragma unroll 3
        for (int r = 0; r < 9; r++) {
            const int rr = (r / 3) * 4 + (r % 3) + prow;
            const float* xr = &xs[(c_l * 12 + rr) * 68 + pb4];
            float4 a4 = *(const float4*)xr;
            float2 b2 = *(const float2*)(xr + 4);
            uint64_t A0 = pack_f32x2(a4.x, a4.y);
            uint64_t A1 = pack_f32x2(a4.z, a4.w);
            uint64_t B0 = pack_f32x2(a4.y, a4.z);
            uint64_t B1 = pack_f32x2(a4.w, b2.x);
            uint64_t C1 = pack_f32x2(b2.x, b2.y);
            const uint64_t* sr = &sd[r * 32];
            #pragma unroll
            for (int t = 0; t < TT; t++) {
                uint64_t s0 = sr[t * 4 + 0];   // s0,s1: one LDS.128 (16B aligned)
                uint64_t s1 = sr[t * 4 + 1];
                uint64_t s2 = sr[t * 4 + 2];   // LDS.64
                ffma2(pa[t][0], s0, A0);  ffma2(pa[t][1], s0, A1);
                ffma2(pa[t][0], s1, B0);  ffma2(pa[t][1], s1, B1);
                ffma2(pa[t][0], s2, A1);  ffma2(pa[t][1], s2, C1);
            }
        }

        float v[TT][4];
        #pragma unroll
        for (int t = 0; t < TT; t++) {
            unpack_f32x2(pa[t][0], v[t][0], v[t][1]);
            unpack_f32x2(pa[t][1], v[t][2], v[t][3]);
        }

        // ---- store taps -> A[k_local][p] tf32, lane-rotated conflict-free STS.32 ----
        #pragma unroll
        for (int t = 0; t < TT; t++) {
            uint32_t rowb = smb + (uint32_t)(A_OFF + (c_l * 8 + t) * SP + prow * 64 + pb4) * 4u;
            #pragma unroll
            for (int s = 0; s < 4; s++) {
                int j = (s + jrot) & 3;
                sts32(rowb + (uint32_t)j * 4u, f2tf32(v[t][j]));
            }
        }
        __syncthreads();

        // ---- GEMM: accumulate this chunk's 128 k via m16n8k8 tf32 ----
        #pragma unroll
        for (int ks = 0; ks < 8; ks++) {
            const int ksl = kh * 8 + ks;          // 0..15 local k-step
            const int kb  = ksl * 8;
            uint32_t abase = smb + (uint32_t)(A_OFF + (kb + (lane & 3)) * SP
                                              + pt2 * 32 + (lane >> 2)) * 4u;
            uint32_t a0[2], a1[2], a2[2], a3[2];
            #pragma unroll
            for (int mf = 0; mf < 2; mf++) {
                uint32_t ab = abase + (uint32_t)(mf * 16) * 4u;
                a0[mf] = lds32(ab);
                a1[mf] = lds32(ab + 8u * 4u);
                a2[mf] = lds32(ab + (uint32_t)(4 * SP) * 4u);
                a3[mf] = lds32(ab + (uint32_t)(4 * SP + 8) * 4u);
            }
            const int ksg = chunk * 16 + ksl;
            #pragma unroll
            for (int nf = 0; nf < 4; nf++) {
                int f = ot * 4 + nf;
                uint2 bf = __ldg(&gw[(f * 32 + ksg) * 32 + lane]);
                mma_tf32(acc[0][nf], a0[0], a1[0], a2[0], a3[0], bf.x, bf.y);
                mma_tf32(acc[1][nf], a0[1], a1[1], a2[1], a3[1], bf.x, bf.y);
            }
        }
    }

    // ---- reduce k-halves through smem (aliases dead A tile) ----
    __syncthreads();
    const int grp = pt2 * 2 + ot;   // 0..7
    if (kh == 1) {
        #pragma unroll
        for (int mf = 0; mf < 2; mf++)
            #pragma unroll
            for (int nf = 0; nf < 4; nf++)
                #pragma unroll
                for (int c = 0; c < 4; c++)
                    red[(grp * 32 + lane) * 33 + (mf * 16 + nf * 4 + c)] = acc[mf][nf][c];
    }
    __syncthreads();

    if (kh == 0) {
        const size_t ostride = (size_t)DDIM * HDIM * WDIM;
        const float* rp = &red[(grp * 32 + lane) * 33];
        #pragma unroll
        for (int nf = 0; nf < 4; nf++) {
            int o0 = ot * 32 + nf * 8 + (lane & 3) * 2;
            float bv0 = __ldg(&bias[o0]);
            float bv1 = __ldg(&bias[o0 + 1]);
            #pragma unroll
            for (int mf = 0; mf < 2; mf++) {
                #pragma unroll
                for (int c = 0; c < 4; c++) {
                    float s = acc[mf][nf][c] + rp[mf * 16 + nf * 4 + c];
                    int o = o0 + (c & 1);
                    int p = pt2 * 32 + mf * 16 + (lane >> 2) + ((c >> 1) & 1) * 8;
                    int h = h0 * 2 + (p >> 6);
                    int w = p & 63;
                    out[((size_t)b * COUT + o) * ostride
                        + (size_t)d0 * HDIM * WDIM + (size_t)h * WDIM + w]
                        = s + ((c & 1) ? bv1 : bv0);
                }
            }
        }
    }
}

extern "C" void kernel_launch(void* const* d_in, const int* in_sizes, int n_in,
                              void* d_out, int out_size) {
    const float* x        = (const float*)d_in[0];
    const float* stencils = (const float*)d_in[1];
    const float* weight   = (const float*)d_in[2];
    const float* bias     = (const float*)d_in[3];
    float* out = (float*)d_out;

    init_wfrag_kernel<<<32, 512>>>(weight);

    cudaFuncSetAttribute(stencilconv3d_kernel,
                         cudaFuncAttributeMaxDynamicSharedMemorySize, SMEM_BYTES);
    dim3 grid(HDIM / 2, DDIM, 4);   // 32 x 32 x 4 = 4096 blocks
    stencilconv3d_kernel<<<grid, 512, SMEM_BYTES>>>(x, stencils, bias, out);
}

// round 7
// speedup vs baseline: 2.3571x; 1.2346x over previous
#include <cuda_runtime.h>
#include <cstdint>

#define CIN   32
#define COUT  64
#define TT    8
#define DDIM  32
#define HDIM  64
#define WDIM  64

// ---------- smem layout (float word offsets) ----------
#define SP      132                    // A tile row stride (words)
#define A_OFF   0
#define A_SIZE  (64 * SP)              // 8448 fl : A taps [k_local(64)][p(128)], tf32
#define XS_OFF  A_SIZE                 // 8448
#define XS_SIZE (8 * 12 * 68)          // 6528 : x chunk 8c x (3d x 4h) x 68w
#define SD_OFF  (XS_OFF + XS_SIZE)     // 14976 (x4 B -> 16B aligned)
#define SD_SIZE (9 * 8 * 4 * 2)        // 576 fl : stencils [r][t][4 u64 padded], dup f32x2
#define SMEM_FLOATS (SD_OFF + SD_SIZE) // 15552
#define SMEM_BYTES  (SMEM_FLOATS * 4)  // 62208 -> 2 blocks/SM

// weight fragments (tf32, mma B-fragment layout), computed once per launch
__device__ uint32_t g_wfrag[COUT * 256];

// ---------- helpers ----------
__device__ __forceinline__ uint32_t smem_u32(const void* p) {
    uint32_t a;
    asm("{ .reg .u64 t; cvta.to.shared.u64 t, %1; cvt.u32.u64 %0, t; }" : "=r"(a) : "l"(p));
    return a;
}
__device__ __forceinline__ uint64_t pack_f32x2(float a, float b) {
    uint64_t r; asm("mov.b64 %0, {%1, %2};" : "=l"(r) : "f"(a), "f"(b)); return r;
}
__device__ __forceinline__ uint64_t dup_f32x2(float v) {
    uint64_t r; asm("mov.b64 %0, {%1, %1};" : "=l"(r) : "f"(v)); return r;
}
__device__ __forceinline__ void ffma2(uint64_t& d, uint64_t a, uint64_t b) {
    asm("fma.rn.f32x2 %0, %1, %2, %0;" : "+l"(d) : "l"(a), "l"(b));
}
__device__ __forceinline__ void unpack_f32x2(uint64_t v, float& lo, float& hi) {
    asm("mov.b64 {%0, %1}, %2;" : "=f"(lo), "=f"(hi) : "l"(v));
}
__device__ __forceinline__ uint32_t f2tf32(float x) {
    uint32_t r; asm("cvt.rna.tf32.f32 %0, %1;" : "=r"(r) : "f"(x)); return r;
}
__device__ __forceinline__ void sts32(uint32_t a, uint32_t v) {
    asm volatile("st.shared.b32 [%0], %1;" :: "r"(a), "r"(v));
}
__device__ __forceinline__ uint32_t lds32(uint32_t a) {
    uint32_t v; asm volatile("ld.shared.b32 %0, [%1];" : "=r"(v) : "r"(a)); return v;
}
__device__ __forceinline__ void mma_tf32(float* c,
                                         uint32_t a0, uint32_t a1, uint32_t a2, uint32_t a3,
                                         uint32_t b0, uint32_t b1) {
    asm volatile("mma.sync.aligned.m16n8k8.row.col.f32.tf32.tf32.f32 "
                 "{%0,%1,%2,%3}, {%4,%5,%6,%7}, {%8,%9}, {%0,%1,%2,%3};"
                 : "+f"(c[0]), "+f"(c[1]), "+f"(c[2]), "+f"(c[3])
                 : "r"(a0), "r"(a1), "r"(a2), "r"(a3), "r"(b0), "r"(b1));
}

// ---------- init kernel: weight -> mma B-fragment layout (tf32), once ----------
__global__ void init_wfrag_kernel(const float* __restrict__ weight) {
    int idx = blockIdx.x * 512 + threadIdx.x;   // 0 .. 16383
    int o = idx >> 8, k = idx & 255;
    int f = o >> 3, ksg = k >> 3;
    int l = ((o & 7) << 2) | (k & 3);
    int r = (k >> 2) & 1;
    g_wfrag[((f * 32 + ksg) * 32 + l) * 2 + r] = f2tf32(weight[idx]);
}

__global__ __launch_bounds__(256, 2)
void stencilconv3d_kernel(const float* __restrict__ x,
                          const float* __restrict__ stencils,
                          const float* __restrict__ bias,
                          float* __restrict__ out) {
    extern __shared__ float sm[];
    float* xs = sm + XS_OFF;
    uint64_t* sd = (uint64_t*)(sm + SD_OFF);
    const uint32_t smb = smem_u32(sm);

    const int h0  = blockIdx.x;   // 0..31 (pair of h rows)
    const int d0  = blockIdx.y;   // 0..31
    const int b   = blockIdx.z;   // 0..3
    const int tid = threadIdx.x;
    const int wid = tid >> 5;     // 0..7
    const int lane = tid & 31;

    // ---- stencils -> sd[r][t][4] (dup f32x2, padded for LDS.128 pairing) ----
    if (tid < TT * 27) {
        int t = tid / 27, s27 = tid - t * 27;
        int r = s27 / 3,  j  = s27 - r * 3;
        sd[r * 32 + t * 4 + j] = dup_f32x2(stencils[(size_t)b * TT * 27 + tid]);
    }

    // phase A thread mapping
    const int c_l  = tid >> 5;            // 0..7 local channel within chunk
    const int prow = (lane >> 4) & 1;     // output h sub-row
    const int pb4  = (lane & 15) << 2;    // 4-point w group
    const int jrot = lane >> 3;           // 0..3 store rotation

    // GEMM warp mapping: wid = pt2*2 + ot ; each warp owns full K
    const int pt2 = wid >> 1;             // 0..3 : 32-point tile
    const int ot  = wid & 1;              // 0..1 : 32-cout tile

    float acc[2][4][4];                   // [m-frag][n-frag][c]
    #pragma unroll
    for (int i = 0; i < 2; i++)
        #pragma unroll
        for (int j = 0; j < 4; j++)
            #pragma unroll
            for (int c = 0; c < 4; c++) acc[i][j][c] = 0.f;

    const size_t x_plane = (size_t)DDIM * HDIM * WDIM;
    const uint2* gw = (const uint2*)g_wfrag;
    const int hbase = h0 * 2 - 1;

    #pragma unroll 1
    for (int chunk = 0; chunk < 4; chunk++) {
        __syncthreads();   // xs + A tile free for reuse

        // ---- load x chunk: 8c x (3d x 4h) x 68w, zero-padded ----
        const float* xb = x + ((size_t)b * CIN + (size_t)chunk * 8) * x_plane;
        {
            int wx = tid % 68;
            int rr = tid / 68;           // 0..3 at start
            int cl = 0;
            for (int idx = tid; idx < XS_SIZE; idx += 256) {
                int dg = d0 + (rr >> 2) - 1;
                int hg = hbase + (rr & 3);
                int wg = wx - 1;
                float v = 0.f;
                if (wx < 66 && (unsigned)dg < DDIM && (unsigned)hg < HDIM && (unsigned)wg < WDIM)
                    v = xb[((size_t)cl * DDIM + dg) * HDIM * WDIM + (size_t)hg * WDIM + wg];
                xs[idx] = v;
                // advance by 256 = 3*68 + 52
                wx += 52; rr += 3;
                if (wx >= 68) { wx -= 68; rr++; }
                if (rr >= 12) { rr -= 12; cl++; }
            }
        }
        __syncthreads();

        // ---- Phase A: 8 taps x 4 points for (c_l, prow, pb4), fp32 FFMA2 ----
        uint64_t pa[TT][2];
        #pragma unroll
        for (int t = 0; t < TT; t++) { pa[t][0] = 0ull; pa[t][1] = 0ull; }

        #pragma unroll 3
        for (int r = 0; r < 9; r++) {
            const int rr = (r / 3) * 4 + (r % 3) + prow;
            const float* xr = &xs[(c_l * 12 + rr) * 68 + pb4];
            float4 a4 = *(const float4*)xr;
            float2 b2 = *(const float2*)(xr + 4);
            uint64_t A0 = pack_f32x2(a4.x, a4.y);
            uint64_t A1 = pack_f32x2(a4.z, a4.w);
            uint64_t B0 = pack_f32x2(a4.y, a4.z);
            uint64_t B1 = pack_f32x2(a4.w, b2.x);
            uint64_t C1 = pack_f32x2(b2.x, b2.y);
            const uint64_t* sr = &sd[r * 32];
            #pragma unroll
            for (int t = 0; t < TT; t++) {
                uint64_t s0 = sr[t * 4 + 0];   // s0,s1: one LDS.128
                uint64_t s1 = sr[t * 4 + 1];
                uint64_t s2 = sr[t * 4 + 2];   // LDS.64
                ffma2(pa[t][0], s0, A0);  ffma2(pa[t][1], s0, A1);
                ffma2(pa[t][0], s1, B0);  ffma2(pa[t][1], s1, B1);
                ffma2(pa[t][0], s2, A1);  ffma2(pa[t][1], s2, C1);
            }
        }

        // ---- store taps -> A[k_local(64)][p] tf32, lane-rotated STS.32 ----
        #pragma unroll
        for (int t = 0; t < TT; t++) {
            float v0, v1, v2, v3;
            unpack_f32x2(pa[t][0], v0, v1);
            unpack_f32x2(pa[t][1], v2, v3);
            uint32_t tf[4] = { f2tf32(v0), f2tf32(v1), f2tf32(v2), f2tf32(v3) };
            uint32_t rowb = smb + (uint32_t)(A_OFF + (c_l * 8 + t) * SP + prow * 64 + pb4) * 4u;
            #pragma unroll
            for (int s = 0; s < 4; s++) {
                int j = (s + jrot) & 3;
                sts32(rowb + (uint32_t)j * 4u, tf[j]);
            }
        }
        __syncthreads();

        // ---- GEMM: this chunk's 64 k via m16n8k8 tf32 (8 k-steps) ----
        #pragma unroll
        for (int ks = 0; ks < 8; ks++) {
            const int kb = ks * 8;
            uint32_t abase = smb + (uint32_t)(A_OFF + (kb + (lane & 3)) * SP
                                              + pt2 * 32 + (lane >> 2)) * 4u;
            uint32_t a0[2], a1[2], a2[2], a3[2];
            #pragma unroll
            for (int mf = 0; mf < 2; mf++) {
                uint32_t ab = abase + (uint32_t)(mf * 16) * 4u;
                a0[mf] = lds32(ab);
                a1[mf] = lds32(ab + 8u * 4u);
                a2[mf] = lds32(ab + (uint32_t)(4 * SP) * 4u);
                a3[mf] = lds32(ab + (uint32_t)(4 * SP + 8) * 4u);
            }
            const int ksg = chunk * 8 + ks;
            #pragma unroll
            for (int nf = 0; nf < 4; nf++) {
                int f = ot * 4 + nf;
                uint2 bf = __ldg(&gw[(f * 32 + ksg) * 32 + lane]);
                mma_tf32(acc[0][nf], a0[0], a1[0], a2[0], a3[0], bf.x, bf.y);
                mma_tf32(acc[1][nf], a0[1], a1[1], a2[1], a3[1], bf.x, bf.y);
            }
        }
    }

    // ---- epilogue: registers -> gmem directly (no k reduction needed) ----
    {
        const size_t ostride = (size_t)DDIM * HDIM * WDIM;
        #pragma unroll
        for (int nf = 0; nf < 4; nf++) {
            int o0 = ot * 32 + nf * 8 + (lane & 3) * 2;
            float bv0 = __ldg(&bias[o0]);
            float bv1 = __ldg(&bias[o0 + 1]);
            #pragma unroll
            for (int mf = 0; mf < 2; mf++) {
                #pragma unroll
                for (int c = 0; c < 4; c++) {
                    float s = acc[mf][nf][c];
                    int o = o0 + (c & 1);
                    int p = pt2 * 32 + mf * 16 + (lane >> 2) + ((c >> 1) & 1) * 8;
                    int h = h0 * 2 + (p >> 6);
                    int w = p & 63;
                    out[((size_t)b * COUT + o) * ostride
                        + (size_t)d0 * HDIM * WDIM + (size_t)h * WDIM + w]
                        = s + ((c & 1) ? bv1 : bv0);
                }
            }
        }
    }
}

extern "C" void kernel_launch(void* const* d_in, const int* in_sizes, int n_in,
                              void* d_out, int out_size) {
    const float* x        = (const float*)d_in[0];
    const float* stencils = (const float*)d_in[1];
    const float* weight   = (const float*)d_in[2];
    const float* bias     = (const float*)d_in[3];
    float* out = (float*)d_out;

    init_wfrag_kernel<<<32, 512>>>(weight);

    cudaFuncSetAttribute(stencilconv3d_kernel,
                         cudaFuncAttributeMaxDynamicSharedMemorySize, SMEM_BYTES);
    dim3 grid(HDIM / 2, DDIM, 4);   // 32 x 32 x 4 = 4096 blocks
    stencilconv3d_kernel<<<grid, 256, SMEM_BYTES>>>(x, stencils, bias, out);
}